// round 10
// baseline (speedup 1.0000x reference)
#include <cuda_runtime.h>

#define CH 64
#define MMAX 50000
#define CAP 80
#define OVF_MAX 8192
#define TILE_M 32

// Allocation-free scratch. Zero-initialized at module load; kernels restore
// the zero invariant each run (seg re-zeroes g_cnt, final re-zeroes g_ovf_n).
__device__ float4 g_S4[MMAX * (CH / 4)];   // segment sums [M][64]
__device__ float  g_deg[MMAX];
__device__ int    g_cnt[MMAX];
__device__ int2   g_bin[MMAX * CAP];       // {src, __float_as_int(ew)}
__device__ int    g_ovf_n;
__device__ int2   g_ovf[OVF_MAX];          // {dst, src}
__device__ float  g_ovf_w[OVF_MAX];

#define FFMA2(acc, a, b) \
    asm("fma.rn.f32x2 %0, %1, %2, %0;" : "+l"(acc) : "l"(a), "l"(b))

// 4 edges/thread, 4 independent atomic chains in flight.
__global__ void fill_kernel(const int* __restrict__ idx,
                            const int* __restrict__ idx1,
                            const float* __restrict__ ew,
                            int E) {
    int t = blockIdx.x * blockDim.x + threadIdx.x;
    int base = t * 4;
    if (base >= E) return;
    if (base + 3 < E) {
        int4   ss = __ldg((const int4*)idx + t);
        int4   dd = __ldg((const int4*)idx1 + t);
        float4 ww = __ldg((const float4*)ew + t);
        int s0 = atomicAdd(&g_cnt[dd.x], 1);
        int s1 = atomicAdd(&g_cnt[dd.y], 1);
        int s2 = atomicAdd(&g_cnt[dd.z], 1);
        int s3 = atomicAdd(&g_cnt[dd.w], 1);
        int srcs[4] = {ss.x, ss.y, ss.z, ss.w};
        int dsts[4] = {dd.x, dd.y, dd.z, dd.w};
        int slots[4] = {s0, s1, s2, s3};
        float ws[4] = {ww.x, ww.y, ww.z, ww.w};
        #pragma unroll
        for (int j = 0; j < 4; j++) {
            if (slots[j] < CAP) {
                g_bin[dsts[j] * CAP + slots[j]] =
                    make_int2(srcs[j], __float_as_int(ws[j]));
            } else {
                int o = atomicAdd(&g_ovf_n, 1);
                if (o < OVF_MAX) {
                    g_ovf[o] = make_int2(dsts[j], srcs[j]);
                    g_ovf_w[o] = ws[j];
                }
            }
        }
    } else {
        for (int e = base; e < E; e++) {
            int dst = idx1[e];
            int slot = atomicAdd(&g_cnt[dst], 1);
            if (slot < CAP) {
                g_bin[dst * CAP + slot] = make_int2(idx[e], __float_as_int(ew[e]));
            } else {
                int o = atomicAdd(&g_ovf_n, 1);
                if (o < OVF_MAX) {
                    g_ovf[o] = make_int2(dst, idx[e]);
                    g_ovf_w[o] = ew[e];
                }
            }
        }
    }
}

// One warp per segment (R7 form). Bin entries: one coalesced int2 load per
// 32-chunk, src broadcast via shfl; row gathers are 256B coalesced float2
// loads. Plain stores — no atomics, no pre-zero. Resets g_cnt for the next
// replay and applies the (normally empty) overflow list inline.
__global__ __launch_bounds__(256) void seg_kernel(const float2* __restrict__ A2,
                                                  int M) {
    int w = (blockIdx.x * blockDim.x + threadIdx.x) >> 5;
    int l = threadIdx.x & 31;
    if (w >= M) return;
    int cntRaw = g_cnt[w];
    if (l == 0) g_cnt[w] = 0;
    int cnt = (cntRaw > CAP) ? CAP : cntRaw;

    float ax = 0.f, ay = 0.f, dl = 0.f;
    for (int c0 = 0; c0 < cnt; c0 += 32) {
        int nn = cnt - c0; if (nn > 32) nn = 32;
        int2 b = (l < nn) ? __ldg(&g_bin[w * CAP + c0 + l]) : make_int2(0, 0);
        if (l < nn) dl += __int_as_float(b.y);
        for (int j = 0; j < nn; j++) {
            int src = __shfl_sync(0xffffffffu, b.x, j);
            float2 v = __ldg(&A2[src * 32 + l]);
            ax += v.x; ay += v.y;
        }
    }

    // Overflow list (normally empty: one broadcast LDG of the counter).
    int novf = g_ovf_n;
    if (novf > OVF_MAX) novf = OVF_MAX;
    for (int i = 0; i < novf; i++) {
        int2 ds = __ldg(&g_ovf[i]);
        if (ds.x == w) {
            float2 v = __ldg(&A2[ds.y * 32 + l]);
            ax += v.x; ay += v.y;
            if (l == 0) dl += g_ovf_w[i];
        }
    }

    #pragma unroll
    for (int o = 16; o; o >>= 1) dl += __shfl_xor_sync(0xffffffffu, dl, o);

    ((float2*)g_S4)[w * 32 + l] = make_float2(ax, ay);
    if (l == 0) g_deg[w] = dl;
}

// Epilogue (R7-proven config): weights smem-resident per block, X/S staged
// per 32-row tile with plain __ldg+STS, FFMA2 compute, 3 blocks/SM.
__global__ __launch_bounds__(256, 3) void final_kernel(
        const float4* __restrict__ A4,
        const int* __restrict__ vn,
        const float* __restrict__ W1,
        const float* __restrict__ b1,
        const float* __restrict__ W2,
        const float* __restrict__ b2,
        const float* __restrict__ Wt,   // weight, layout [k][c]
        float* __restrict__ out,
        int M, int numTiles) {
    extern __shared__ float4 sm[];
    float4* sW1v = sm;                   // [16][64]
    float4* sW2v = sm + 1024;            // [16][64]
    float4* sWv  = sm + 2048;            // [16][64]
    float4* sX   = sm + 3072;            // [32][16]
    float4* sS   = sm + 3584;            // [32][16]
    float*  sDeg = (float*)(sm + 4096);  // [32]

    int tid = threadIdx.x;
    int c = tid & 63;
    int g = tid >> 6;
    float b1c = __ldg(&b1[c]);
    float b2c = __ldg(&b2[c]);

    if (blockIdx.x == 0 && tid == 0) g_ovf_n = 0;   // reset for next replay

    const float4* W1v4 = (const float4*)W1;
    const float4* W2v4 = (const float4*)W2;
    for (int i = tid; i < 1024; i += 256) {
        int kk = i >> 6, cc = i & 63;
        sW1v[i] = __ldg(&W1v4[cc * 16 + kk]);
        sW2v[i] = __ldg(&W2v4[cc * 16 + kk]);
        int k0 = kk * 4;
        sWv[i] = make_float4(__ldg(&Wt[(k0 + 0) * CH + cc]),
                             __ldg(&Wt[(k0 + 1) * CH + cc]),
                             __ldg(&Wt[(k0 + 2) * CH + cc]),
                             __ldg(&Wt[(k0 + 3) * CH + cc]));
    }

    for (int tile = blockIdx.x; tile < numTiles; tile += gridDim.x) {
        int m0 = tile * TILE_M;
        __syncthreads();
        for (int i = tid; i < TILE_M * 16; i += 256) {
            int r = i >> 4, q = i & 15;
            int m = m0 + r;
            int mc = (m < M) ? m : 0;
            int rowA = (m < M) ? vn[m] : 0;
            sX[i] = __ldg(&A4[rowA * 16 + q]);
            sS[i] = g_S4[mc * 16 + q];
        }
        if (tid < TILE_M) {
            int m = m0 + tid;
            sDeg[tid] = (m < M) ? g_deg[m] : 0.f;
        }
        __syncthreads();

        unsigned long long a1[8], a2[8], a3[8];
        #pragma unroll
        for (int r = 0; r < 8; r++) { a1[r] = 0ull; a2[r] = 0ull; a3[r] = 0ull; }

        #pragma unroll
        for (int kk = 0; kk < 16; kk++) {
            ulonglong2 w1 = *(const ulonglong2*)&sW1v[kk * 64 + c];
            ulonglong2 w2 = *(const ulonglong2*)&sW2v[kk * 64 + c];
            ulonglong2 wv = *(const ulonglong2*)&sWv [kk * 64 + c];
            #pragma unroll
            for (int r = 0; r < 8; r++) {
                ulonglong2 x = *(const ulonglong2*)&sX[(g * 8 + r) * 16 + kk];
                ulonglong2 s = *(const ulonglong2*)&sS[(g * 8 + r) * 16 + kk];
                FFMA2(a1[r], x.x, w1.x); FFMA2(a1[r], x.y, w1.y);
                FFMA2(a2[r], x.x, w2.x); FFMA2(a2[r], x.y, w2.y);
                FFMA2(a3[r], s.x, wv.x); FFMA2(a3[r], s.y, wv.y);
            }
        }

        #pragma unroll
        for (int r = 0; r < 8; r++) {
            int m = m0 + g * 8 + r;
            if (m < M) {
                unsigned lo, hi;
                float s1, s2, s3;
                asm("mov.b64 {%0,%1}, %2;" : "=r"(lo), "=r"(hi) : "l"(a1[r]));
                s1 = __uint_as_float(lo) + __uint_as_float(hi);
                asm("mov.b64 {%0,%1}, %2;" : "=r"(lo), "=r"(hi) : "l"(a2[r]));
                s2 = __uint_as_float(lo) + __uint_as_float(hi);
                asm("mov.b64 {%0,%1}, %2;" : "=r"(lo), "=r"(hi) : "l"(a3[r]));
                s3 = __uint_as_float(lo) + __uint_as_float(hi);
                float d = sDeg[g * 8 + r];
                out[m * CH + c] = d * (s1 + b1c) + s3 + s2 + b2c;
            }
        }
    }
}

extern "C" void kernel_launch(void* const* d_in, const int* in_sizes, int n_in,
                              void* d_out, int out_size) {
    const float* A    = (const float*)d_in[0];   // [N, 64] f32
    const int*   vn   = (const int*)d_in[1];     // [M] int32
    const int*   idx  = (const int*)d_in[2];     // [E] int32
    const int*   idx1 = (const int*)d_in[3];     // [E] int32
    const float* ew   = (const float*)d_in[4];   // [E] f32
    const float* Wt   = (const float*)d_in[5];   // [64, 64] = [CIN][COUT]
    const float* W1   = (const float*)d_in[6];   // [64, 64] = [COUT][CIN]
    const float* b1   = (const float*)d_in[7];   // [64]
    const float* W2   = (const float*)d_in[8];   // [64, 64]
    const float* b2   = (const float*)d_in[9];   // [64]
    float* out = (float*)d_out;

    int M = in_sizes[1];
    int E = in_sizes[2];

    {
        int threads4 = (E + 3) / 4;
        fill_kernel<<<(threads4 + 255) / 256, 256>>>(idx, idx1, ew, E);
    }
    {
        int blocks = (M * 32 + 255) / 256;
        seg_kernel<<<blocks, 256>>>((const float2*)A, M);
    }
    {
        int smemBytes = 4096 * sizeof(float4) + TILE_M * sizeof(float); // 65664
        cudaFuncSetAttribute(final_kernel,
                             cudaFuncAttributeMaxDynamicSharedMemorySize,
                             smemBytes);
        int numTiles = (M + TILE_M - 1) / TILE_M;
        int blocks = 444;                         // 3 blocks/SM
        if (blocks > numTiles) blocks = numTiles;
        final_kernel<<<blocks, 256, smemBytes>>>(
            (const float4*)A, vn, W1, b1, W2, b2, Wt, out, M, numTiles);
    }
}

// round 11
// speedup vs baseline: 1.5283x; 1.5283x over previous
#include <cuda_runtime.h>

#define CH 64
#define MMAX 50000
#define CAP 80
#define OVF_MAX 8192
#define TILE_M 32

// Allocation-free scratch.
__device__ float4 g_S4[MMAX * (CH / 4)];   // segment sums [M][64]
__device__ float  g_deg[MMAX];
__device__ int    g_cnt[MMAX];
__device__ int2   g_bin[MMAX * CAP];       // {src, __float_as_int(ew)}
__device__ int    g_ovf_n;
__device__ int2   g_ovf[OVF_MAX];          // {dst, src}
__device__ float  g_ovf_w[OVF_MAX];

#define FFMA2(acc, a, b) \
    asm("fma.rn.f32x2 %0, %1, %2, %0;" : "+l"(acc) : "l"(a), "l"(b))

__global__ void zero_kernel(int M) {
    int i = blockIdx.x * blockDim.x + threadIdx.x;
    if (i < M) g_cnt[i] = 0;
    if (i == 0) g_ovf_n = 0;
}

// Bin each edge under its destination. Packed 8B store (src + ew bits).
// Overflow (not expected at CAP=80) goes to a tiny list, applied by fixup.
__global__ void fill_kernel(const int2* __restrict__ idx2,
                            const int2* __restrict__ idx12,
                            const float2* __restrict__ ew2,
                            int E2, int E) {
    int t = blockIdx.x * blockDim.x + threadIdx.x;
    if (t >= E2) return;
    int2 ss = __ldg(&idx2[t]);
    int2 dd = __ldg(&idx12[t]);
    float2 ww = __ldg(&ew2[t]);
    int n = E - t * 2;   // handle odd tail
    #pragma unroll
    for (int j = 0; j < 2; j++) {
        if (j >= n) break;
        int src = j ? ss.y : ss.x;
        int dst = j ? dd.y : dd.x;
        float w = j ? ww.y : ww.x;
        int slot = atomicAdd(&g_cnt[dst], 1);
        if (slot < CAP) {
            g_bin[dst * CAP + slot] = make_int2(src, __float_as_int(w));
        } else {
            int o = atomicAdd(&g_ovf_n, 1);
            if (o < OVF_MAX) {
                g_ovf[o] = make_int2(dst, src);
                g_ovf_w[o] = w;
            }
        }
    }
}

// One warp per segment. Bin entries loaded with ONE coalesced int2 load per
// 32-chunk; src broadcast via shfl. Plain stores — no atomics, no pre-zero.
__global__ __launch_bounds__(256) void seg_kernel(const float2* __restrict__ A2,
                                                  int M) {
    int w = (blockIdx.x * blockDim.x + threadIdx.x) >> 5;
    int l = threadIdx.x & 31;
    if (w >= M) return;
    int cnt = g_cnt[w];
    if (cnt > CAP) cnt = CAP;

    float ax = 0.f, ay = 0.f, dl = 0.f;
    for (int c0 = 0; c0 < cnt; c0 += 32) {
        int nn = cnt - c0; if (nn > 32) nn = 32;
        int2 b = (l < nn) ? __ldg(&g_bin[w * CAP + c0 + l]) : make_int2(0, 0);
        if (l < nn) dl += __int_as_float(b.y);
        for (int j = 0; j < nn; j++) {
            int src = __shfl_sync(0xffffffffu, b.x, j);
            float2 v = __ldg(&A2[src * 32 + l]);
            ax += v.x; ay += v.y;
        }
    }
    #pragma unroll
    for (int o = 16; o; o >>= 1) dl += __shfl_xor_sync(0xffffffffu, dl, o);

    ((float2*)g_S4)[w * 32 + l] = make_float2(ax, ay);
    if (l == 0) g_deg[w] = dl;
}

// Apply overflow edges (normally zero of them) on top of seg's stores.
__global__ void fixup_kernel(const float4* __restrict__ A4) {
    int n = g_ovf_n;
    if (n > OVF_MAX) n = OVF_MAX;
    for (int t = threadIdx.x; t < n * 16; t += blockDim.x) {
        int e = t >> 4, q = t & 15;
        int2 ds = g_ovf[e];
        float4 v = __ldg(&A4[ds.y * 16 + q]);
        float4* p = &g_S4[ds.x * 16 + q];
        asm volatile("red.global.add.v4.f32 [%0], {%1,%2,%3,%4};"
                     :: "l"(p), "f"(v.x), "f"(v.y), "f"(v.z), "f"(v.w)
                     : "memory");
        if (q == 0) atomicAdd(&g_deg[ds.x], g_ovf_w[e]);
    }
}

// Epilogue with packed f32x2 FMAs. Per thread: 1 column x 8 rows; per kk-step
// the float4 operands are consumed as two natural b64 pairs -> fma.rn.f32x2
// with zero packing overhead. Accumulators are (even,odd) b64 pairs.
__global__ __launch_bounds__(256, 3) void final_kernel(
        const float4* __restrict__ A4,
        const int* __restrict__ vn,
        const float* __restrict__ W1,
        const float* __restrict__ b1,
        const float* __restrict__ W2,
        const float* __restrict__ b2,
        const float* __restrict__ Wt,   // weight, layout [k][c]
        float* __restrict__ out,
        int M, int numTiles) {
    extern __shared__ float4 sm[];
    float4* sW1v = sm;                   // [16][64]: kk -> W1[c][4kk..4kk+3]
    float4* sW2v = sm + 1024;            // [16][64]
    float4* sWv  = sm + 2048;            // [16][64]: kk -> Wt[4kk..4kk+3][c]
    float4* sX   = sm + 3072;            // [32][16]
    float4* sS   = sm + 3584;            // [32][16]
    float*  sDeg = (float*)(sm + 4096);  // [32]

    int tid = threadIdx.x;
    int c = tid & 63;
    int g = tid >> 6;
    float b1c = __ldg(&b1[c]);
    float b2c = __ldg(&b2[c]);

    const float4* W1v4 = (const float4*)W1;
    const float4* W2v4 = (const float4*)W2;
    for (int i = tid; i < 1024; i += 256) {
        int kk = i >> 6, cc = i & 63;
        sW1v[i] = __ldg(&W1v4[cc * 16 + kk]);
        sW2v[i] = __ldg(&W2v4[cc * 16 + kk]);
        int k0 = kk * 4;
        sWv[i] = make_float4(__ldg(&Wt[(k0 + 0) * CH + cc]),
                             __ldg(&Wt[(k0 + 1) * CH + cc]),
                             __ldg(&Wt[(k0 + 2) * CH + cc]),
                             __ldg(&Wt[(k0 + 3) * CH + cc]));
    }

    for (int tile = blockIdx.x; tile < numTiles; tile += gridDim.x) {
        int m0 = tile * TILE_M;
        __syncthreads();
        for (int i = tid; i < TILE_M * 16; i += 256) {
            int r = i >> 4, q = i & 15;
            int m = m0 + r;
            int mc = (m < M) ? m : 0;
            int rowA = (m < M) ? vn[m] : 0;
            sX[i] = __ldg(&A4[rowA * 16 + q]);
            sS[i] = g_S4[mc * 16 + q];
        }
        if (tid < TILE_M) {
            int m = m0 + tid;
            sDeg[tid] = (m < M) ? g_deg[m] : 0.f;
        }
        __syncthreads();

        unsigned long long a1[8], a2[8], a3[8];
        #pragma unroll
        for (int r = 0; r < 8; r++) { a1[r] = 0ull; a2[r] = 0ull; a3[r] = 0ull; }

        #pragma unroll
        for (int kk = 0; kk < 16; kk++) {
            ulonglong2 w1 = *(const ulonglong2*)&sW1v[kk * 64 + c];
            ulonglong2 w2 = *(const ulonglong2*)&sW2v[kk * 64 + c];
            ulonglong2 wv = *(const ulonglong2*)&sWv [kk * 64 + c];
            #pragma unroll
            for (int r = 0; r < 8; r++) {
                ulonglong2 x = *(const ulonglong2*)&sX[(g * 8 + r) * 16 + kk];
                ulonglong2 s = *(const ulonglong2*)&sS[(g * 8 + r) * 16 + kk];
                FFMA2(a1[r], x.x, w1.x); FFMA2(a1[r], x.y, w1.y);
                FFMA2(a2[r], x.x, w2.x); FFMA2(a2[r], x.y, w2.y);
                FFMA2(a3[r], s.x, wv.x); FFMA2(a3[r], s.y, wv.y);
            }
        }

        #pragma unroll
        for (int r = 0; r < 8; r++) {
            int m = m0 + g * 8 + r;
            if (m < M) {
                unsigned lo, hi;
                float s1, s2, s3;
                asm("mov.b64 {%0,%1}, %2;" : "=r"(lo), "=r"(hi) : "l"(a1[r]));
                s1 = __uint_as_float(lo) + __uint_as_float(hi);
                asm("mov.b64 {%0,%1}, %2;" : "=r"(lo), "=r"(hi) : "l"(a2[r]));
                s2 = __uint_as_float(lo) + __uint_as_float(hi);
                asm("mov.b64 {%0,%1}, %2;" : "=r"(lo), "=r"(hi) : "l"(a3[r]));
                s3 = __uint_as_float(lo) + __uint_as_float(hi);
                float d = sDeg[g * 8 + r];
                out[m * CH + c] = d * (s1 + b1c) + s3 + s2 + b2c;
            }
        }
    }
}

extern "C" void kernel_launch(void* const* d_in, const int* in_sizes, int n_in,
                              void* d_out, int out_size) {
    const float* A    = (const float*)d_in[0];   // [N, 64] f32
    const int*   vn   = (const int*)d_in[1];     // [M] int32
    const int*   idx  = (const int*)d_in[2];     // [E] int32
    const int*   idx1 = (const int*)d_in[3];     // [E] int32
    const float* ew   = (const float*)d_in[4];   // [E] f32
    const float* Wt   = (const float*)d_in[5];   // [64, 64] = [CIN][COUT]
    const float* W1   = (const float*)d_in[6];   // [64, 64] = [COUT][CIN]
    const float* b1   = (const float*)d_in[7];   // [64]
    const float* W2   = (const float*)d_in[8];   // [64, 64]
    const float* b2   = (const float*)d_in[9];   // [64]
    float* out = (float*)d_out;

    int M = in_sizes[1];
    int E = in_sizes[2];

    zero_kernel<<<(M + 255) / 256, 256>>>(M);
    {
        int E2 = (E + 1) / 2;
        fill_kernel<<<(E2 + 255) / 256, 256>>>(
            (const int2*)idx, (const int2*)idx1, (const float2*)ew, E2, E);
    }
    {
        int blocks = (M * 32 + 255) / 256;
        seg_kernel<<<blocks, 256>>>((const float2*)A, M);
    }
    fixup_kernel<<<1, 256>>>((const float4*)A);
    {
        int smemBytes = 4096 * sizeof(float4) + TILE_M * sizeof(float); // 65664
        cudaFuncSetAttribute(final_kernel,
                             cudaFuncAttributeMaxDynamicSharedMemorySize,
                             smemBytes);
        int numTiles = (M + TILE_M - 1) / TILE_M;
        int blocks = 444;
        if (blocks > numTiles) blocks = numTiles;
        final_kernel<<<blocks, 256, smemBytes>>>(
            (const float4*)A, vn, W1, b1, W2, b2, Wt, out, M, numTiles);
    }
}